// round 1
// baseline (speedup 1.0000x reference)
#include <cuda_runtime.h>
#include <math.h>

// ---------------------------------------------------------------------------
// EBT_GRC beam-search tree composition. N=256, S=32, D=512, CH=2048, BEAM=5.
// Row-pool + index-array representation; per-step batched fp32 GEMMs.
// ---------------------------------------------------------------------------

#define NB    256
#define SEQ   32
#define DIM   512
#define CH    2048
#define BEAMK 5
#define MAXR  192               // 32 + 31*5 = 187 rows max per batch element
#define NTASK (NB * BEAMK)      // 1280 grc tasks per step

// ------------------------- device scratch (static) -------------------------
__device__ float g_rows[NB * MAXR * DIM];   // row pool (content vectors)
__device__ float g_u  [NB * MAXR * DIM];    // cached row @ Wd1[:512]
__device__ float g_v  [NB * MAXR * DIM];    // cached row @ Wd1[512:]
__device__ float g_tmp[NB * SEQ * DIM];     // pre-LN init GEMM output
__device__ float g_hcat[NTASK * CH];        // gelu(cat@Wc1+bc1)
__device__ float g_cc  [NTASK * CH];        // hcat@Wc2+bc2
__device__ int   g_idx [NB * BEAMK * SEQ];  // per-beam logical pos -> row id
__device__ float g_accu[NB * BEAMK];
__device__ int   g_task_l[NTASK];           // per-task left row id (within n)
__device__ int   g_task_r[NTASK];

__device__ __forceinline__ float gelu_f(float x) {
    return 0.5f * x * (1.0f + erff(x * 0.70710678118654752440f));
}

// ------------------------------- GEMM --------------------------------------
// C[M,N] = act( A[M,K] @ B[K,N] + bias ), 128x64 tile, BK=16, 256 threads.
// a_mode/c_mode: 0 = contiguous (lda/ldc), 1 = row-pool mapping
//   row(m) = (m / rpn)*MAXR + base + (m % rpn), row stride DIM.
#define BM 128
#define BN 64
#define BK 16

__global__ __launch_bounds__(256) void gemm_kernel(
    const float* __restrict__ A, const float* __restrict__ Bw,
    const float* __restrict__ bias, float* __restrict__ Cc,
    int K, int lda, int ldb, int ldc,
    int a_mode, int a_base, int a_rpn,
    int c_mode, int c_base, int c_rpn, int act)
{
    __shared__ float As[BK][BM + 4];
    __shared__ float Bs[BK][BN + 4];
    const int tid = threadIdx.x;
    const int m0 = blockIdx.y * BM;
    const int n0 = blockIdx.x * BN;
    const int tx = tid & 15;          // 16 col groups * 4
    const int ty = tid >> 4;          // 16 row groups * 8

    const int a_m = tid >> 1;         // 0..127
    const int a_k = (tid & 1) << 3;   // 0 or 8
    const float* arow;
    {
        int m = m0 + a_m;
        if (a_mode == 0) arow = A + (size_t)m * lda;
        else { int n = m / a_rpn; int r = m - n * a_rpn;
               arow = A + ((size_t)n * MAXR + a_base + r) * DIM; }
    }
    const int b_k = tid >> 4;         // 0..15
    const int b_j = (tid & 15) << 2;  // 0..60
    const float* bptr = Bw + (size_t)b_k * ldb + n0 + b_j;

    float acc[8][4];
#pragma unroll
    for (int i = 0; i < 8; i++)
#pragma unroll
        for (int j = 0; j < 4; j++) acc[i][j] = 0.f;

    for (int k0 = 0; k0 < K; k0 += BK) {
        float4 av0 = *(const float4*)(arow + k0 + a_k);
        float4 av1 = *(const float4*)(arow + k0 + a_k + 4);
        As[a_k + 0][a_m] = av0.x; As[a_k + 1][a_m] = av0.y;
        As[a_k + 2][a_m] = av0.z; As[a_k + 3][a_m] = av0.w;
        As[a_k + 4][a_m] = av1.x; As[a_k + 5][a_m] = av1.y;
        As[a_k + 6][a_m] = av1.z; As[a_k + 7][a_m] = av1.w;
        *(float4*)&Bs[b_k][b_j] = *(const float4*)(bptr + (size_t)k0 * ldb);
        __syncthreads();
#pragma unroll
        for (int k = 0; k < BK; k++) {
            float4 a0 = *(const float4*)&As[k][ty << 3];
            float4 a1 = *(const float4*)&As[k][(ty << 3) + 4];
            float4 b4 = *(const float4*)&Bs[k][tx << 2];
            float ar[8] = {a0.x, a0.y, a0.z, a0.w, a1.x, a1.y, a1.z, a1.w};
            float br[4] = {b4.x, b4.y, b4.z, b4.w};
#pragma unroll
            for (int i = 0; i < 8; i++)
#pragma unroll
                for (int j = 0; j < 4; j++)
                    acc[i][j] = fmaf(ar[i], br[j], acc[i][j]);
        }
        __syncthreads();
    }

    float4 bi4 = make_float4(0.f, 0.f, 0.f, 0.f);
    if (bias) bi4 = *(const float4*)(bias + n0 + (tx << 2));
#pragma unroll
    for (int i = 0; i < 8; i++) {
        int m = m0 + (ty << 3) + i;
        float* crow;
        if (c_mode == 0) crow = Cc + (size_t)m * ldc;
        else { int n = m / c_rpn; int r = m - n * c_rpn;
               crow = Cc + ((size_t)n * MAXR + c_base + r) * DIM; }
        float4 o;
        o.x = acc[i][0] + bi4.x; o.y = acc[i][1] + bi4.y;
        o.z = acc[i][2] + bi4.z; o.w = acc[i][3] + bi4.w;
        if (act) { o.x = gelu_f(o.x); o.y = gelu_f(o.y);
                   o.z = gelu_f(o.z); o.w = gelu_f(o.w); }
        *(float4*)(crow + n0 + (tx << 2)) = o;
    }
}

// cat-GEMM: A row t = [rows[l_t] | rows[r_t]] (K=1024), B=Wc1, gelu -> g_hcat
__global__ __launch_bounds__(256) void gemm_cat_kernel(
    const float* __restrict__ Wc1, const float* __restrict__ bc1)
{
    __shared__ float As[BK][BM + 4];
    __shared__ float Bs[BK][BN + 4];
    const int tid = threadIdx.x;
    const int m0 = blockIdx.y * BM;
    const int n0 = blockIdx.x * BN;
    const int tx = tid & 15;
    const int ty = tid >> 4;

    const int a_m = tid >> 1;
    const int a_k = (tid & 1) << 3;
    const int t  = m0 + a_m;
    const int n  = t / BEAMK;
    const float* lrow = g_rows + ((size_t)n * MAXR + g_task_l[t]) * DIM;
    const float* rrow = g_rows + ((size_t)n * MAXR + g_task_r[t]) * DIM;

    const int b_k = tid >> 4;
    const int b_j = (tid & 15) << 2;
    const float* bptr = Wc1 + (size_t)b_k * CH + n0 + b_j;

    float acc[8][4];
#pragma unroll
    for (int i = 0; i < 8; i++)
#pragma unroll
        for (int j = 0; j < 4; j++) acc[i][j] = 0.f;

    for (int k0 = 0; k0 < 2 * DIM; k0 += BK) {
        int kk = k0 + a_k;
        const float* src = (kk < DIM) ? (lrow + kk) : (rrow + kk - DIM);
        float4 av0 = *(const float4*)src;
        float4 av1 = *(const float4*)(src + 4);
        As[a_k + 0][a_m] = av0.x; As[a_k + 1][a_m] = av0.y;
        As[a_k + 2][a_m] = av0.z; As[a_k + 3][a_m] = av0.w;
        As[a_k + 4][a_m] = av1.x; As[a_k + 5][a_m] = av1.y;
        As[a_k + 6][a_m] = av1.z; As[a_k + 7][a_m] = av1.w;
        *(float4*)&Bs[b_k][b_j] = *(const float4*)(bptr + (size_t)k0 * CH);
        __syncthreads();
#pragma unroll
        for (int k = 0; k < BK; k++) {
            float4 a0 = *(const float4*)&As[k][ty << 3];
            float4 a1 = *(const float4*)&As[k][(ty << 3) + 4];
            float4 b4 = *(const float4*)&Bs[k][tx << 2];
            float ar[8] = {a0.x, a0.y, a0.z, a0.w, a1.x, a1.y, a1.z, a1.w};
            float br[4] = {b4.x, b4.y, b4.z, b4.w};
#pragma unroll
            for (int i = 0; i < 8; i++)
#pragma unroll
                for (int j = 0; j < 4; j++)
                    acc[i][j] = fmaf(ar[i], br[j], acc[i][j]);
        }
        __syncthreads();
    }

    float4 bi4 = *(const float4*)(bc1 + n0 + (tx << 2));
#pragma unroll
    for (int i = 0; i < 8; i++) {
        int m = m0 + (ty << 3) + i;
        float* crow = g_hcat + (size_t)m * CH;
        float4 o;
        o.x = gelu_f(acc[i][0] + bi4.x); o.y = gelu_f(acc[i][1] + bi4.y);
        o.z = gelu_f(acc[i][2] + bi4.z); o.w = gelu_f(acc[i][3] + bi4.w);
        *(float4*)(crow + n0 + (tx << 2)) = o;
    }
}

// ------------------------ selection (per batch elem) ------------------------
__global__ __launch_bounds__(256) void select_kernel(
    int B, int S_cur, int topk, int base_dest,
    const float* __restrict__ bd1, const float* __restrict__ Wd2,
    const float* __restrict__ bd2)
{
    const int n = blockIdx.x;
    const int tid = threadIdx.x;
    __shared__ float sw[BEAMK][SEQ];
    __shared__ int   sold[BEAMK][SEQ];
    __shared__ int   snew[BEAMK][SEQ];
    __shared__ float saccu[BEAMK];
    __shared__ float cscore[BEAMK * BEAMK];
    __shared__ int   cparent[BEAMK * BEAMK];
    __shared__ int   cpos[BEAMK * BEAMK];
    __shared__ int   ssel[BEAMK];
    __shared__ float snacc[BEAMK];
    __shared__ float sbd1[DIM];
    __shared__ float swd2[DIM];

    for (int t = tid; t < B * (S_cur + 1); t += 256) {
        int b = t / (S_cur + 1), s = t - b * (S_cur + 1);
        sold[b][s] = g_idx[(n * BEAMK + b) * SEQ + s];
    }
    for (int d = tid; d < DIM; d += 256) { sbd1[d] = bd1[d]; swd2[d] = Wd2[d]; }
    if (tid < B) saccu[tid] = g_accu[n * BEAMK + tid];
    __syncthreads();

    if (S_cur == 1) {   // final step: grc each beam's only pair; accu unchanged
        if (tid < B) {
            g_task_l[n * BEAMK + tid] = sold[tid][0];
            g_task_r[n * BEAMK + tid] = sold[tid][1];
            g_idx[(n * BEAMK + tid) * SEQ] = base_dest + tid;
        }
        return;
    }

    // pair scores w[b][s] from cached u,v
    const int lane = tid & 31, wid = tid >> 5;
    const float* un = g_u + (size_t)n * MAXR * DIM;
    const float* vn = g_v + (size_t)n * MAXR * DIM;
    for (int p = wid; p < B * S_cur; p += 8) {
        int b = p / S_cur, s = p - b * S_cur;
        const float* ul = un + (size_t)sold[b][s] * DIM;
        const float* vr = vn + (size_t)sold[b][s + 1] * DIM;
        float acc = 0.f;
        for (int d = lane; d < DIM; d += 32)
            acc += gelu_f(ul[d] + vr[d] + sbd1[d]) * swd2[d];
#pragma unroll
        for (int o = 16; o; o >>= 1) acc += __shfl_xor_sync(0xffffffffu, acc, o);
        if (lane == 0) sw[b][s] = acc + bd2[0];
    }
    __syncthreads();

    // per-beam softmax + top-k (jax.lax.top_k tie-break: lower index first)
    if (tid < B) {
        int b = tid;
        float m = -1e30f;
        for (int s = 0; s < S_cur; s++) m = fmaxf(m, sw[b][s]);
        float sum = 0.f;
        for (int s = 0; s < S_cur; s++) sum += expf(sw[b][s] - m);
        sum += 1e-20f;
        unsigned used = 0u;
        for (int k = 0; k < topk; k++) {
            float bv = -1e30f; int bi = 0;
            for (int s = 0; s < S_cur; s++) {
                if (used & (1u << s)) continue;
                if (sw[b][s] > bv) { bv = sw[b][s]; bi = s; }
            }
            used |= 1u << bi;
            float soft = expf(bv - m) / sum;
            cscore [b * topk + k] = saccu[b] + logf(soft + 1e-20f);
            cparent[b * topk + k] = b;
            cpos   [b * topk + k] = bi;
        }
    }
    __syncthreads();

    // beam pruning: top BEAM of B*topk candidates
    if (tid == 0) {
        int nc = B * topk;
        if (nc <= BEAMK) {
            for (int k = 0; k < nc; k++) ssel[k] = k;
        } else {
            unsigned used = 0u;
            for (int k = 0; k < BEAMK; k++) {
                float bv = -1e30f; int bi = 0;
                for (int c = 0; c < nc; c++) {
                    if (used & (1u << c)) continue;
                    if (cscore[c] > bv) { bv = cscore[c]; bi = c; }
                }
                used |= 1u << bi;
                ssel[k] = bi;
            }
        }
    }
    __syncthreads();

    if (tid < BEAMK) {
        int c = ssel[tid];
        snacc[tid] = cscore[c];
        int p = cparent[c], j = cpos[c];
        g_task_l[n * BEAMK + tid] = sold[p][j];
        g_task_r[n * BEAMK + tid] = sold[p][j + 1];
    }
    __syncthreads();
    for (int t = tid; t < BEAMK * S_cur; t += 256) {
        int k = t / S_cur, s = t - k * S_cur;
        int c = ssel[k]; int p = cparent[c], j = cpos[c];
        snew[k][s] = (s < j) ? sold[p][s] : (s == j ? base_dest + k : sold[p][s + 1]);
    }
    __syncthreads();
    for (int t = tid; t < BEAMK * S_cur; t += 256) {
        int k = t / S_cur, s = t - k * S_cur;
        g_idx[(n * BEAMK + k) * SEQ + s] = snew[k][s];
    }
    if (tid < BEAMK) g_accu[n * BEAMK + tid] = snacc[tid];
}

// ---------------------- gating + layernorm epilogue -------------------------
__global__ __launch_bounds__(256) void gate_ln_kernel(
    int base_dest, const float* __restrict__ gw, const float* __restrict__ bw)
{
    const int t = blockIdx.x;                 // task 0..1279
    const int n = t / BEAMK;
    const int k = t - n * BEAMK;
    const int tid = threadIdx.x;
    const float* c    = g_cc   + (size_t)t * CH;
    const float* lrow = g_rows + ((size_t)n * MAXR + g_task_l[t]) * DIM;
    const float* rrow = g_rows + ((size_t)n * MAXR + g_task_r[t]) * DIM;
    __shared__ float sout[DIM];
    __shared__ float red[2][8];
    float lsum = 0.f, lsq = 0.f;
#pragma unroll
    for (int it = 0; it < 2; it++) {
        int d = tid + it * 256;
        float c0 = c[d], c1 = c[DIM + d], c2 = c[2 * DIM + d], c3 = c[3 * DIM + d];
        float mx = fmaxf(c0, fmaxf(c1, c2));
        float e0 = expf(c0 - mx), e1 = expf(c1 - mx), e2 = expf(c2 - mx);
        float inv = 1.0f / (e0 + e1 + e2);
        float o = (e0 * lrow[d] + e1 * rrow[d] + e2 * c3) * inv;
        sout[d] = o; lsum += o; lsq += o * o;
    }
#pragma unroll
    for (int o = 16; o; o >>= 1) {
        lsum += __shfl_xor_sync(0xffffffffu, lsum, o);
        lsq  += __shfl_xor_sync(0xffffffffu, lsq , o);
    }
    if ((tid & 31) == 0) { red[0][tid >> 5] = lsum; red[1][tid >> 5] = lsq; }
    __syncthreads();
    if (tid < 32) {
        float a = (tid < 8) ? red[0][tid] : 0.f;
        float b = (tid < 8) ? red[1][tid] : 0.f;
#pragma unroll
        for (int o = 4; o; o >>= 1) {
            a += __shfl_xor_sync(0xffffffffu, a, o);
            b += __shfl_xor_sync(0xffffffffu, b, o);
        }
        if (tid == 0) { red[0][0] = a; red[1][0] = b; }
    }
    __syncthreads();
    float mu   = red[0][0] * (1.0f / DIM);
    float var  = red[1][0] * (1.0f / DIM) - mu * mu;
    float rstd = rsqrtf(var + 1e-5f);
    float* outr = g_rows + ((size_t)n * MAXR + base_dest + k) * DIM;
#pragma unroll
    for (int it = 0; it < 2; it++) {
        int d = tid + it * 256;
        outr[d] = (sout[d] - mu) * rstd * gw[d] + bw[d];
    }
}

// --------------------- init: layernorm of x@Wi+bi ---------------------------
__global__ __launch_bounds__(256) void ln_init_kernel(
    const float* __restrict__ gw, const float* __restrict__ bw)
{
    const int t = blockIdx.x;                  // n*32+s
    const int n = t >> 5, s = t & 31;
    const int tid = threadIdx.x;
    const float* in = g_tmp + (size_t)t * DIM;
    float* outr = g_rows + ((size_t)n * MAXR + s) * DIM;
    __shared__ float red[2][8];
    float v0 = in[tid], v1 = in[tid + 256];
    float lsum = v0 + v1, lsq = v0 * v0 + v1 * v1;
#pragma unroll
    for (int o = 16; o; o >>= 1) {
        lsum += __shfl_xor_sync(0xffffffffu, lsum, o);
        lsq  += __shfl_xor_sync(0xffffffffu, lsq , o);
    }
    if ((tid & 31) == 0) { red[0][tid >> 5] = lsum; red[1][tid >> 5] = lsq; }
    __syncthreads();
    if (tid < 32) {
        float a = (tid < 8) ? red[0][tid] : 0.f;
        float b = (tid < 8) ? red[1][tid] : 0.f;
#pragma unroll
        for (int o = 4; o; o >>= 1) {
            a += __shfl_xor_sync(0xffffffffu, a, o);
            b += __shfl_xor_sync(0xffffffffu, b, o);
        }
        if (tid == 0) { red[0][0] = a; red[1][0] = b; }
    }
    __syncthreads();
    float mu   = red[0][0] * (1.0f / DIM);
    float var  = red[1][0] * (1.0f / DIM) - mu * mu;
    float rstd = rsqrtf(var + 1e-5f);
    outr[tid]       = (v0 - mu) * rstd * gw[tid]       + bw[tid];
    outr[tid + 256] = (v1 - mu) * rstd * gw[tid + 256] + bw[tid + 256];
}

__global__ void init_state_kernel()
{
    int n = blockIdx.x;
    if (threadIdx.x < SEQ) g_idx[n * BEAMK * SEQ + threadIdx.x] = threadIdx.x;
    if (threadIdx.x == 0) g_accu[n * BEAMK] = 0.f;
}

__global__ __launch_bounds__(256) void final_kernel(float* __restrict__ out)
{
    const int n = blockIdx.x;
    const int tid = threadIdx.x;
    __shared__ float wts[BEAMK];
    __shared__ int   rid[BEAMK];
    if (tid < BEAMK) rid[tid] = g_idx[(n * BEAMK + tid) * SEQ];
    if (tid == 0) {
        float a[BEAMK]; float m = -1e30f;
        for (int b = 0; b < BEAMK; b++) { a[b] = g_accu[n * BEAMK + b]; m = fmaxf(m, a[b]); }
        float s = 0.f;
        for (int b = 0; b < BEAMK; b++) { a[b] = expf(a[b] - m); s += a[b]; }
        for (int b = 0; b < BEAMK; b++) wts[b] = a[b] / s;
    }
    __syncthreads();
#pragma unroll
    for (int it = 0; it < 2; it++) {
        int d = tid + it * 256;
        float acc = 0.f;
        for (int b = 0; b < BEAMK; b++)
            acc += wts[b] * g_rows[((size_t)n * MAXR + rid[b]) * DIM + d];
        out[n * DIM + d] = acc;
    }
}

// --------------------------------- host ------------------------------------
extern "C" void kernel_launch(void* const* d_in, const int* in_sizes, int n_in,
                              void* d_out, int out_size)
{
    const float* x   = (const float*)d_in[0];
    const float* Wi  = (const float*)d_in[2];
    const float* bi  = (const float*)d_in[3];
    const float* g1  = (const float*)d_in[4];
    const float* b1  = (const float*)d_in[5];
    const float* Wd1 = (const float*)d_in[6];
    const float* bd1 = (const float*)d_in[7];
    const float* Wd2 = (const float*)d_in[8];
    const float* bd2 = (const float*)d_in[9];
    const float* Wc1 = (const float*)d_in[10];
    const float* bc1 = (const float*)d_in[11];
    const float* Wc2 = (const float*)d_in[12];
    const float* bc2 = (const float*)d_in[13];
    const float* g2  = (const float*)d_in[14];
    const float* b2  = (const float*)d_in[15];
    float* out = (float*)d_out;

    float *rows_p, *u_p, *v_p, *tmp_p, *hcat_p, *c_p;
    cudaGetSymbolAddress((void**)&rows_p, g_rows);
    cudaGetSymbolAddress((void**)&u_p,    g_u);
    cudaGetSymbolAddress((void**)&v_p,    g_v);
    cudaGetSymbolAddress((void**)&tmp_p,  g_tmp);
    cudaGetSymbolAddress((void**)&hcat_p, g_hcat);
    cudaGetSymbolAddress((void**)&c_p,    g_cc);

    dim3 blk(256);

    // init: tmp = x@Wi+bi ; rows = LN(tmp) ; u,v caches for initial rows
    gemm_kernel<<<dim3(DIM / BN, (NB * SEQ) / BM), blk>>>(
        x, Wi, bi, tmp_p, DIM, DIM, DIM, DIM, 0, 0, 0, 0, 0, 0, 0);
    ln_init_kernel<<<NB * SEQ, blk>>>(g1, b1);
    init_state_kernel<<<NB, 32>>>();
    gemm_kernel<<<dim3(DIM / BN, (NB * SEQ) / BM), blk>>>(
        rows_p, Wd1, nullptr, u_p, DIM, 0, DIM, 0, 1, 0, SEQ, 1, 0, SEQ, 0);
    gemm_kernel<<<dim3(DIM / BN, (NB * SEQ) / BM), blk>>>(
        rows_p, Wd1 + DIM * DIM, nullptr, v_p, DIM, 0, DIM, 0, 1, 0, SEQ, 1, 0, SEQ, 0);

    for (int step = 0; step < SEQ - 1; step++) {
        int S_cur = (SEQ - 1) - step;
        int B = (step == 0) ? 1 : BEAMK;
        int topk = S_cur < BEAMK ? S_cur : BEAMK;
        int base = SEQ + step * BEAMK;

        select_kernel<<<NB, blk>>>(B, S_cur, topk, base, bd1, Wd2, bd2);
        gemm_cat_kernel<<<dim3(CH / BN, NTASK / BM), blk>>>(Wc1, bc1);
        gemm_kernel<<<dim3(CH / BN, NTASK / BM), blk>>>(
            hcat_p, Wc2, bc2, c_p, CH, CH, CH, CH, 0, 0, 0, 0, 0, 0, 0);
        gate_ln_kernel<<<NTASK, blk>>>(base, g2, b2);
        if (step < SEQ - 2) {
            gemm_kernel<<<dim3(DIM / BN, NTASK / BM), blk>>>(
                rows_p, Wd1, nullptr, u_p, DIM, 0, DIM, 0,
                1, base, BEAMK, 1, base, BEAMK, 0);
            gemm_kernel<<<dim3(DIM / BN, NTASK / BM), blk>>>(
                rows_p, Wd1 + DIM * DIM, nullptr, v_p, DIM, 0, DIM, 0,
                1, base, BEAMK, 1, base, BEAMK, 0);
        }
    }

    final_kernel<<<NB, blk>>>(out);
    (void)in_sizes; (void)n_in; (void)out_size;
}